// round 12
// baseline (speedup 1.0000x reference)
#include <cuda_runtime.h>
#include <cuda_fp16.h>
#include <cstdint>

#define BATCH 8192
#define IN_F  2048
#define OUT_F 2048
#define QB    7.0f
#define EPSF  1e-5f

// ---------------- scratch (static device arrays; no cudaMalloc) -------------
__device__ __half g_xq[(size_t)BATCH * IN_F];    // 32 MB quantized activations
__device__ __half g_wbin[(size_t)OUT_F * IN_F];  // 8 MB  sign weights
__device__ float  g_beta[OUT_F];
__device__ float  g_rs[BATCH];

// ---------------- fused prep: register-resident rows ------------------------
__global__ __launch_bounds__(256) void prep_kernel(const float* __restrict__ x,
                                                   const float* __restrict__ w) {
    const int tid = threadIdx.x, lane = tid & 31, wid = tid >> 5;
    __shared__ float red[3][8];

    float v[8];
    if (blockIdx.x < 2048) {
        const int o = blockIdx.x;
        const float4* row = (const float4*)(w + (size_t)o * IN_F) + tid * 2;
        float4 p0 = row[0], p1 = row[1];
        v[0]=p0.x; v[1]=p0.y; v[2]=p0.z; v[3]=p0.w;
        v[4]=p1.x; v[5]=p1.y; v[6]=p1.z; v[7]=p1.w;

        float s0 = 0.f, s1 = 0.f;
        #pragma unroll
        for (int i = 0; i < 8; i++) { s0 += v[i]; s1 += fabsf(v[i]); }
        #pragma unroll
        for (int off = 16; off; off >>= 1) {
            s0 += __shfl_xor_sync(0xffffffffu, s0, off);
            s1 += __shfl_xor_sync(0xffffffffu, s1, off);
        }
        if (lane == 0) { red[0][wid] = s0; red[1][wid] = s1; }
        __syncthreads();
        float t0 = 0.f, t1 = 0.f;
        #pragma unroll
        for (int i = 0; i < 8; i++) { t0 += red[0][i]; t1 += red[1][i]; }
        float mean = t0 * (1.0f / IN_F);
        if (tid == 0) g_beta[o] = t1 * (1.0f / IN_F);

        __half h[8];
        #pragma unroll
        for (int i = 0; i < 8; i++) {
            float c = v[i] - mean;
            h[i] = __float2half_rn((c > 0.f) ? 1.0f : ((c < 0.f) ? -1.0f : 0.0f));
        }
        *((uint4*)(g_wbin + (size_t)o * IN_F) + tid) = *(const uint4*)h;
    } else {
        const int b = blockIdx.x - 2048;
        const float4* row = (const float4*)(x + (size_t)b * IN_F) + tid * 2;
        float4 p0 = row[0], p1 = row[1];
        v[0]=p0.x; v[1]=p0.y; v[2]=p0.z; v[3]=p0.w;
        v[4]=p1.x; v[5]=p1.y; v[6]=p1.z; v[7]=p1.w;

        float s0 = 0.f, s1 = 0.f;
        #pragma unroll
        for (int i = 0; i < 8; i++) { s0 += v[i]; s1 += v[i] * v[i]; }
        #pragma unroll
        for (int off = 16; off; off >>= 1) {
            s0 += __shfl_xor_sync(0xffffffffu, s0, off);
            s1 += __shfl_xor_sync(0xffffffffu, s1, off);
        }
        if (lane == 0) { red[0][wid] = s0; red[1][wid] = s1; }
        __syncthreads();
        float t0 = 0.f, t1 = 0.f;
        #pragma unroll
        for (int i = 0; i < 8; i++) { t0 += red[0][i]; t1 += red[1][i]; }
        float mu   = t0 * (1.0f / IN_F);
        float var  = t1 * (1.0f / IN_F) - mu * mu;
        float rstd = rsqrtf(var + EPSF);

        float lm = 0.f;
        #pragma unroll
        for (int i = 0; i < 8; i++) lm = fmaxf(lm, fabsf(v[i] - mu));
        #pragma unroll
        for (int off = 16; off; off >>= 1)
            lm = fmaxf(lm, __shfl_xor_sync(0xffffffffu, lm, off));
        if (lane == 0) red[2][wid] = lm;
        __syncthreads();
        float mx = 0.f;
        #pragma unroll
        for (int i = 0; i < 8; i++) mx = fmaxf(mx, red[2][i]);
        float gama = fmaxf(mx * rstd, EPSF);
        float s = rstd * (QB / gama);
        const float clo = -QB + EPSF, chi = QB - EPSF;

        __half h[8];
        #pragma unroll
        for (int i = 0; i < 8; i++) {
            float q = (v[i] - mu) * s;
            h[i] = __float2half_rn(fminf(fmaxf(q, clo), chi));
        }
        *((uint4*)(g_xq + (size_t)b * IN_F) + tid) = *(const uint4*)h;
        if (tid == 0) g_rs[b] = gama * (1.0f / QB);
    }
}

// ---------------- GEMM: y = xq @ wbin^T, mbarrier pipeline -----------------
// CTA tile 64x128, 4-stage ring, 2 CTAs/SM
#define BM 64
#define BN 128
#define BK 64
#define SST 72            // smem row stride in halves (144B rows, conflict-free)
#define KT  (IN_F / BK)   // 32
#define NSTG 4
#define NTHR 256

__device__ __forceinline__ void mma_f16(float* c, const uint32_t* a, const uint32_t* b) {
    asm volatile(
        "mma.sync.aligned.m16n8k16.row.col.f32.f16.f16.f32 "
        "{%0,%1,%2,%3}, {%4,%5,%6,%7}, {%8,%9}, {%0,%1,%2,%3};\n"
        : "+f"(c[0]), "+f"(c[1]), "+f"(c[2]), "+f"(c[3])
        : "r"(a[0]), "r"(a[1]), "r"(a[2]), "r"(a[3]), "r"(b[0]), "r"(b[1]));
}

__device__ __forceinline__ void ldsm4(uint32_t* r, uint32_t addr) {
    asm volatile("ldmatrix.sync.aligned.m8n8.x4.shared.b16 {%0,%1,%2,%3}, [%4];\n"
                 : "=r"(r[0]), "=r"(r[1]), "=r"(r[2]), "=r"(r[3]) : "r"(addr));
}

__device__ __forceinline__ void cpa16(uint32_t d, const void* s) {
    asm volatile("cp.async.cg.shared.global [%0], [%1], 16;\n" :: "r"(d), "l"(s));
}
__device__ __forceinline__ void mbar_init(uint32_t a, uint32_t cnt) {
    asm volatile("mbarrier.init.shared.b64 [%0], %1;" :: "r"(a), "r"(cnt) : "memory");
}
__device__ __forceinline__ void mbar_arrive(uint32_t a) {
    asm volatile("mbarrier.arrive.shared.b64 _, [%0];" :: "r"(a) : "memory");
}
__device__ __forceinline__ void cpa_mbar_arrive_noinc(uint32_t a) {
    asm volatile("cp.async.mbarrier.arrive.noinc.shared.b64 [%0];" :: "r"(a) : "memory");
}
__device__ __forceinline__ void mbar_wait(uint32_t a, uint32_t parity) {
    asm volatile(
        "{\n\t.reg .pred P;\n\t"
        "LW%=:\n\t"
        "mbarrier.try_wait.parity.acquire.cta.shared::cta.b64 P, [%0], %1, 0x989680;\n\t"
        "@P bra LD%=;\n\t"
        "bra LW%=;\n\t"
        "LD%=:\n\t}"
        :: "r"(a), "r"(parity) : "memory");
}

__global__ __launch_bounds__(NTHR, 2) void gemm_kernel(const float* __restrict__ bias,
                                                       float* __restrict__ out) {
    extern __shared__ __half sm[];
    // layout: [0,64): mbarriers (full[4] @0..24; empty[4] @32..56); tiles @64
    __half* sA = sm + 32;                        // NSTG * BM * SST halves
    __half* sB = sm + 32 + NSTG * BM * SST;      // NSTG * BN * SST halves
    const uint32_t mbarBase = (uint32_t)__cvta_generic_to_shared(sm);
    const uint32_t fullM  = mbarBase;            // + 8*s
    const uint32_t emptyM = mbarBase + 32;       // + 8*s

    const int tid = threadIdx.x;
    const int lane = tid & 31, w = tid >> 5;
    const int wm = w >> 2, wn = w & 3;           // 2x4 warp grid, warp tile 32x32
    const int warp_m = wm * 32, warp_n = wn * 32;
    const int m0 = blockIdx.y * BM;
    const int n0 = blockIdx.x * BN;

    const uint32_t baseA = (uint32_t)__cvta_generic_to_shared(sA);
    const uint32_t baseB = (uint32_t)__cvta_generic_to_shared(sB);

    const __half* __restrict__ Aq = g_xq;
    const __half* __restrict__ Bw = g_wbin;

    // per-lane ldmatrix address components
    const int matA = lane >> 3, ra = lane & 7;
    const int a_row_off = (matA & 1) * 8 + ra;
    const int a_col_off = (matA >> 1) * 8;
    const int b_n_off   = ((matA >> 1) ? 8 : 0) + ra;
    const int b_k_off   = (matA & 1) * 8;

    float acc[2][4][4];
    #pragma unroll
    for (int a = 0; a < 2; a++)
        #pragma unroll
        for (int b = 0; b < 4; b++)
            #pragma unroll
            for (int c = 0; c < 4; c++) acc[a][b][c] = 0.f;

    if (tid == 0) {
        #pragma unroll
        for (int s = 0; s < NSTG; s++) {
            mbar_init(fullM + 8 * s, NTHR);   // 256 async arrivals per load
            mbar_init(emptyM + 8 * s, 8);     // 8 warp-arrivals per consume
        }
    }
    __syncthreads();

    // tile loader: A 512 + B 1024 chunks of 16B; 6 per thread; signals full[s]
    auto load_tile = [&](int kt, int buf) {
        const int k0 = kt * BK;
        #pragma unroll
        for (int i = 0; i < 2; i++) {            // A: 512 chunks
            int c = tid + i * NTHR;
            int r = c >> 3, kc = c & 7;
            uint32_t doff = (uint32_t)((buf * BM * SST + r * SST + kc * 8) * 2);
            cpa16(baseA + doff, Aq + (size_t)(m0 + r) * IN_F + k0 + kc * 8);
        }
        #pragma unroll
        for (int i = 0; i < 4; i++) {            // B: 1024 chunks
            int c = tid + i * NTHR;
            int r = c >> 3, kc = c & 7;
            uint32_t doff = (uint32_t)((buf * BN * SST + r * SST + kc * 8) * 2);
            cpa16(baseB + doff, Bw + (size_t)(n0 + r) * IN_F + k0 + kc * 8);
        }
        cpa_mbar_arrive_noinc(fullM + 8 * buf);
    };

    load_tile(0, 0);
    load_tile(1, 1);

    for (int kt = 0; kt < KT; ++kt) {
        const int s = kt % NSTG;
        mbar_wait(fullM + 8 * s, (kt / NSTG) & 1);

        const uint32_t bufAEl = (uint32_t)(s * BM * SST);
        const uint32_t bufBEl = (uint32_t)(s * BN * SST);
        #pragma unroll
        for (int ks = 0; ks < 4; ++ks) {
            uint32_t aa[2][4], bb[2][4];
            #pragma unroll
            for (int mt = 0; mt < 2; ++mt) {
                uint32_t off = (bufAEl + (uint32_t)((warp_m + mt * 16 + a_row_off) * SST
                                                    + ks * 16 + a_col_off)) * 2;
                ldsm4(aa[mt], baseA + off);
            }
            #pragma unroll
            for (int p = 0; p < 2; ++p) {
                uint32_t off = (bufBEl + (uint32_t)((warp_n + p * 16 + b_n_off) * SST
                                                    + ks * 16 + b_k_off)) * 2;
                ldsm4(bb[p], baseB + off);
            }
            #pragma unroll
            for (int mt = 0; mt < 2; ++mt)
                #pragma unroll
                for (int p = 0; p < 2; ++p) {
                    mma_f16(acc[mt][2 * p],     aa[mt], &bb[p][0]);
                    mma_f16(acc[mt][2 * p + 1], aa[mt], &bb[p][2]);
                }
        }

        // done reading stage s
        __syncwarp();
        if (lane == 0) mbar_arrive(emptyM + 8 * s);

        // load tile kt+2 into stage s2=(kt+2)%4; prior tenant = tile kt-2
        if (kt + 2 < KT) {
            const int s2 = (kt + 2) % NSTG;
            if (kt >= 2) mbar_wait(emptyM + 8 * s2, ((kt - 2) / NSTG) & 1);
            load_tile(kt + 2, s2);
        }
    }

    // epilogue: y = acc * beta[n] * rs[m] + bias[n]
    const int l4 = lane >> 2, l2 = (lane & 3) * 2;
    #pragma unroll
    for (int mt = 0; mt < 2; ++mt) {
        int mrow = m0 + warp_m + mt * 16 + l4;
        float s0 = g_rs[mrow];
        float s1 = g_rs[mrow + 8];
        #pragma unroll
        for (int nt = 0; nt < 4; ++nt) {
            int n = n0 + warp_n + nt * 8 + l2;
            float be0 = g_beta[n], be1 = g_beta[n + 1];
            float bi0 = bias[n],   bi1 = bias[n + 1];
            float2 r0, r1;
            r0.x = acc[mt][nt][0] * be0 * s0 + bi0;
            r0.y = acc[mt][nt][1] * be1 * s0 + bi1;
            r1.x = acc[mt][nt][2] * be0 * s1 + bi0;
            r1.y = acc[mt][nt][3] * be1 * s1 + bi1;
            *reinterpret_cast<float2*>(out + (size_t)mrow * OUT_F + n) = r0;
            *reinterpret_cast<float2*>(out + (size_t)(mrow + 8) * OUT_F + n) = r1;
        }
    }
}

// ---------------- launch ----------------------------------------------------
extern "C" void kernel_launch(void* const* d_in, const int* in_sizes, int n_in,
                              void* d_out, int out_size) {
    const float* x    = (const float*)d_in[0];
    const float* wgt  = (const float*)d_in[1];
    const float* bias = (const float*)d_in[2];
    float* out = (float*)d_out;

    prep_kernel<<<2048 + BATCH, 256>>>(x, wgt);

    const int smem = 64 + NSTG * (BM + BN) * SST * (int)sizeof(__half);  // 110656
    cudaFuncSetAttribute(gemm_kernel, cudaFuncAttributeMaxDynamicSharedMemorySize, smem);
    dim3 grid(OUT_F / BN, BATCH / BM);   // (16, 128) = 2048 CTAs
    gemm_kernel<<<grid, NTHR, smem>>>(bias, out);
}

// round 13
// speedup vs baseline: 1.0271x; 1.0271x over previous
#include <cuda_runtime.h>
#include <cuda_fp16.h>
#include <cstdint>

#define BATCH 8192
#define IN_F  2048
#define OUT_F 2048
#define QB    7.0f
#define EPSF  1e-5f

// ---------------- scratch (static device arrays; no cudaMalloc) -------------
__device__ __half g_xq[(size_t)BATCH * IN_F];    // 32 MB quantized activations
__device__ __half g_wbin[(size_t)OUT_F * IN_F];  // 8 MB  sign weights
__device__ float  g_beta[OUT_F];
__device__ float  g_rs[BATCH];

// ---------------- fused prep: register-resident rows ------------------------
__global__ __launch_bounds__(256) void prep_kernel(const float* __restrict__ x,
                                                   const float* __restrict__ w) {
    const int tid = threadIdx.x, lane = tid & 31, wid = tid >> 5;
    __shared__ float red[3][8];

    float v[8];
    if (blockIdx.x < 2048) {
        const int o = blockIdx.x;
        const float4* row = (const float4*)(w + (size_t)o * IN_F) + tid * 2;
        float4 p0 = row[0], p1 = row[1];
        v[0]=p0.x; v[1]=p0.y; v[2]=p0.z; v[3]=p0.w;
        v[4]=p1.x; v[5]=p1.y; v[6]=p1.z; v[7]=p1.w;

        float s0 = 0.f, s1 = 0.f;
        #pragma unroll
        for (int i = 0; i < 8; i++) { s0 += v[i]; s1 += fabsf(v[i]); }
        #pragma unroll
        for (int off = 16; off; off >>= 1) {
            s0 += __shfl_xor_sync(0xffffffffu, s0, off);
            s1 += __shfl_xor_sync(0xffffffffu, s1, off);
        }
        if (lane == 0) { red[0][wid] = s0; red[1][wid] = s1; }
        __syncthreads();
        float t0 = 0.f, t1 = 0.f;
        #pragma unroll
        for (int i = 0; i < 8; i++) { t0 += red[0][i]; t1 += red[1][i]; }
        float mean = t0 * (1.0f / IN_F);
        if (tid == 0) g_beta[o] = t1 * (1.0f / IN_F);

        __half h[8];
        #pragma unroll
        for (int i = 0; i < 8; i++) {
            float c = v[i] - mean;
            h[i] = __float2half_rn((c > 0.f) ? 1.0f : ((c < 0.f) ? -1.0f : 0.0f));
        }
        *((uint4*)(g_wbin + (size_t)o * IN_F) + tid) = *(const uint4*)h;
    } else {
        const int b = blockIdx.x - 2048;
        const float4* row = (const float4*)(x + (size_t)b * IN_F) + tid * 2;
        float4 p0 = row[0], p1 = row[1];
        v[0]=p0.x; v[1]=p0.y; v[2]=p0.z; v[3]=p0.w;
        v[4]=p1.x; v[5]=p1.y; v[6]=p1.z; v[7]=p1.w;

        float s0 = 0.f, s1 = 0.f;
        #pragma unroll
        for (int i = 0; i < 8; i++) { s0 += v[i]; s1 += v[i] * v[i]; }
        #pragma unroll
        for (int off = 16; off; off >>= 1) {
            s0 += __shfl_xor_sync(0xffffffffu, s0, off);
            s1 += __shfl_xor_sync(0xffffffffu, s1, off);
        }
        if (lane == 0) { red[0][wid] = s0; red[1][wid] = s1; }
        __syncthreads();
        float t0 = 0.f, t1 = 0.f;
        #pragma unroll
        for (int i = 0; i < 8; i++) { t0 += red[0][i]; t1 += red[1][i]; }
        float mu   = t0 * (1.0f / IN_F);
        float var  = t1 * (1.0f / IN_F) - mu * mu;
        float rstd = rsqrtf(var + EPSF);

        float lm = 0.f;
        #pragma unroll
        for (int i = 0; i < 8; i++) lm = fmaxf(lm, fabsf(v[i] - mu));
        #pragma unroll
        for (int off = 16; off; off >>= 1)
            lm = fmaxf(lm, __shfl_xor_sync(0xffffffffu, lm, off));
        if (lane == 0) red[2][wid] = lm;
        __syncthreads();
        float mx = 0.f;
        #pragma unroll
        for (int i = 0; i < 8; i++) mx = fmaxf(mx, red[2][i]);
        float gama = fmaxf(mx * rstd, EPSF);
        float s = rstd * (QB / gama);
        const float clo = -QB + EPSF, chi = QB - EPSF;

        __half h[8];
        #pragma unroll
        for (int i = 0; i < 8; i++) {
            float q = (v[i] - mu) * s;
            h[i] = __float2half_rn(fminf(fmaxf(q, clo), chi));
        }
        *((uint4*)(g_xq + (size_t)b * IN_F) + tid) = *(const uint4*)h;
        if (tid == 0) g_rs[b] = gama * (1.0f / QB);
    }
}

// ---------------- GEMM: y = xq @ wbin^T, mbarrier pipeline -----------------
// CTA tile 128x64, 128 threads (4 warps of 64x32), 4-stage ring, 2 CTAs/SM
#define BM 128
#define BN 64
#define BK 64
#define SST 72            // smem row stride in halves (144B rows, conflict-free)
#define KT  (IN_F / BK)   // 32
#define NSTG 4
#define NTHR 128

__device__ __forceinline__ void mma_f16(float* c, const uint32_t* a, const uint32_t* b) {
    asm volatile(
        "mma.sync.aligned.m16n8k16.row.col.f32.f16.f16.f32 "
        "{%0,%1,%2,%3}, {%4,%5,%6,%7}, {%8,%9}, {%0,%1,%2,%3};\n"
        : "+f"(c[0]), "+f"(c[1]), "+f"(c[2]), "+f"(c[3])
        : "r"(a[0]), "r"(a[1]), "r"(a[2]), "r"(a[3]), "r"(b[0]), "r"(b[1]));
}

__device__ __forceinline__ void ldsm4(uint32_t* r, uint32_t addr) {
    asm volatile("ldmatrix.sync.aligned.m8n8.x4.shared.b16 {%0,%1,%2,%3}, [%4];\n"
                 : "=r"(r[0]), "=r"(r[1]), "=r"(r[2]), "=r"(r[3]) : "r"(addr));
}

__device__ __forceinline__ void cpa16(uint32_t d, const void* s) {
    asm volatile("cp.async.cg.shared.global [%0], [%1], 16;\n" :: "r"(d), "l"(s));
}
__device__ __forceinline__ void mbar_init(uint32_t a, uint32_t cnt) {
    asm volatile("mbarrier.init.shared.b64 [%0], %1;" :: "r"(a), "r"(cnt) : "memory");
}
__device__ __forceinline__ void mbar_arrive(uint32_t a) {
    asm volatile("mbarrier.arrive.shared.b64 _, [%0];" :: "r"(a) : "memory");
}
__device__ __forceinline__ void cpa_mbar_arrive_noinc(uint32_t a) {
    asm volatile("cp.async.mbarrier.arrive.noinc.shared.b64 [%0];" :: "r"(a) : "memory");
}
__device__ __forceinline__ void mbar_wait(uint32_t a, uint32_t parity) {
    asm volatile(
        "{\n\t.reg .pred P;\n\t"
        "LW%=:\n\t"
        "mbarrier.try_wait.parity.acquire.cta.shared::cta.b64 P, [%0], %1, 0x989680;\n\t"
        "@P bra LD%=;\n\t"
        "bra LW%=;\n\t"
        "LD%=:\n\t}"
        :: "r"(a), "r"(parity) : "memory");
}

__global__ __launch_bounds__(NTHR, 2) void gemm_kernel(const float* __restrict__ bias,
                                                       float* __restrict__ out) {
    extern __shared__ __half sm[];
    // layout: [0,64): mbarriers (full[4] @0..24; empty[4] @32..56); tiles @64
    __half* sA = sm + 32;                        // NSTG * BM * SST halves
    __half* sB = sm + 32 + NSTG * BM * SST;      // NSTG * BN * SST halves
    const uint32_t mbarBase = (uint32_t)__cvta_generic_to_shared(sm);
    const uint32_t fullM  = mbarBase;            // + 8*s
    const uint32_t emptyM = mbarBase + 32;       // + 8*s

    const int tid = threadIdx.x;
    const int lane = tid & 31, w = tid >> 5;
    const int wm = w >> 1, wn = w & 1;           // 2x2 warp grid, warp tile 64x32
    const int warp_m = wm * 64, warp_n = wn * 32;
    const int m0 = blockIdx.y * BM;
    const int n0 = blockIdx.x * BN;

    const uint32_t baseA = (uint32_t)__cvta_generic_to_shared(sA);
    const uint32_t baseB = (uint32_t)__cvta_generic_to_shared(sB);

    const __half* __restrict__ Aq = g_xq;
    const __half* __restrict__ Bw = g_wbin;

    // per-lane ldmatrix address components
    const int matA = lane >> 3, ra = lane & 7;
    const int a_row_off = (matA & 1) * 8 + ra;
    const int a_col_off = (matA >> 1) * 8;
    const int b_n_off   = ((matA >> 1) ? 8 : 0) + ra;
    const int b_k_off   = (matA & 1) * 8;

    float acc[4][4][4];
    #pragma unroll
    for (int a = 0; a < 4; a++)
        #pragma unroll
        for (int b = 0; b < 4; b++)
            #pragma unroll
            for (int c = 0; c < 4; c++) acc[a][b][c] = 0.f;

    if (tid == 0) {
        #pragma unroll
        for (int s = 0; s < NSTG; s++) {
            mbar_init(fullM + 8 * s, NTHR);   // 128 async arrivals per load
            mbar_init(emptyM + 8 * s, 4);     // 4 warp-arrivals per consume
        }
    }
    __syncthreads();

    // tile loader: A 1024 + B 512 chunks of 16B; 12 per thread @128 threads
    auto load_tile = [&](int kt, int buf) {
        const int k0 = kt * BK;
        #pragma unroll
        for (int i = 0; i < 8; i++) {            // A: 1024 chunks
            int c = tid + i * NTHR;
            int r = c >> 3, kc = c & 7;
            uint32_t doff = (uint32_t)((buf * BM * SST + r * SST + kc * 8) * 2);
            cpa16(baseA + doff, Aq + (size_t)(m0 + r) * IN_F + k0 + kc * 8);
        }
        #pragma unroll
        for (int i = 0; i < 4; i++) {            // B: 512 chunks
            int c = tid + i * NTHR;
            int r = c >> 3, kc = c & 7;
            uint32_t doff = (uint32_t)((buf * BN * SST + r * SST + kc * 8) * 2);
            cpa16(baseB + doff, Bw + (size_t)(n0 + r) * IN_F + k0 + kc * 8);
        }
        cpa_mbar_arrive_noinc(fullM + 8 * buf);
    };

    load_tile(0, 0);
    load_tile(1, 1);

    for (int kt = 0; kt < KT; ++kt) {
        const int s = kt % NSTG;
        mbar_wait(fullM + 8 * s, (kt / NSTG) & 1);

        const uint32_t bufAEl = (uint32_t)(s * BM * SST);
        const uint32_t bufBEl = (uint32_t)(s * BN * SST);
        #pragma unroll
        for (int ks = 0; ks < 4; ++ks) {
            uint32_t aa[4][4], bb[2][4];
            #pragma unroll
            for (int mt = 0; mt < 4; ++mt) {
                uint32_t off = (bufAEl + (uint32_t)((warp_m + mt * 16 + a_row_off) * SST
                                                    + ks * 16 + a_col_off)) * 2;
                ldsm4(aa[mt], baseA + off);
            }
            #pragma unroll
            for (int p = 0; p < 2; ++p) {
                uint32_t off = (bufBEl + (uint32_t)((warp_n + p * 16 + b_n_off) * SST
                                                    + ks * 16 + b_k_off)) * 2;
                ldsm4(bb[p], baseB + off);
            }
            #pragma unroll
            for (int mt = 0; mt < 4; ++mt)
                #pragma unroll
                for (int p = 0; p < 2; ++p) {
                    mma_f16(acc[mt][2 * p],     aa[mt], &bb[p][0]);
                    mma_f16(acc[mt][2 * p + 1], aa[mt], &bb[p][2]);
                }
        }

        // done reading stage s
        __syncwarp();
        if (lane == 0) mbar_arrive(emptyM + 8 * s);

        // load tile kt+2 into stage s2=(kt+2)%4; prior tenant = tile kt-2
        if (kt + 2 < KT) {
            const int s2 = (kt + 2) % NSTG;
            if (kt >= 2) mbar_wait(emptyM + 8 * s2, ((kt - 2) / NSTG) & 1);
            load_tile(kt + 2, s2);
        }
    }

    // epilogue: y = acc * beta[n] * rs[m] + bias[n]
    const int l4 = lane >> 2, l2 = (lane & 3) * 2;
    #pragma unroll
    for (int mt = 0; mt < 4; ++mt) {
        int mrow = m0 + warp_m + mt * 16 + l4;
        float s0 = g_rs[mrow];
        float s1 = g_rs[mrow + 8];
        #pragma unroll
        for (int nt = 0; nt < 4; ++nt) {
            int n = n0 + warp_n + nt * 8 + l2;
            float be0 = g_beta[n], be1 = g_beta[n + 1];
            float bi0 = bias[n],   bi1 = bias[n + 1];
            float2 r0, r1;
            r0.x = acc[mt][nt][0] * be0 * s0 + bi0;
            r0.y = acc[mt][nt][1] * be1 * s0 + bi1;
            r1.x = acc[mt][nt][2] * be0 * s1 + bi0;
            r1.y = acc[mt][nt][3] * be1 * s1 + bi1;
            *reinterpret_cast<float2*>(out + (size_t)mrow * OUT_F + n) = r0;
            *reinterpret_cast<float2*>(out + (size_t)(mrow + 8) * OUT_F + n) = r1;
        }
    }
}

// ---------------- launch ----------------------------------------------------
extern "C" void kernel_launch(void* const* d_in, const int* in_sizes, int n_in,
                              void* d_out, int out_size) {
    const float* x    = (const float*)d_in[0];
    const float* wgt  = (const float*)d_in[1];
    const float* bias = (const float*)d_in[2];
    float* out = (float*)d_out;

    prep_kernel<<<2048 + BATCH, 256>>>(x, wgt);

    const int smem = 64 + NSTG * (BM + BN) * SST * (int)sizeof(__half);  // 110656
    cudaFuncSetAttribute(gemm_kernel, cudaFuncAttributeMaxDynamicSharedMemorySize, smem);
    dim3 grid(OUT_F / BN, BATCH / BM);   // (32, 64) = 2048 CTAs
    gemm_kernel<<<grid, NTHR, smem>>>(bias, out);
}

// round 14
// speedup vs baseline: 1.1198x; 1.0903x over previous
#include <cuda_runtime.h>
#include <cuda_fp16.h>
#include <cstdint>

#define BATCH 8192
#define IN_F  2048
#define OUT_F 2048
#define QB    7.0f
#define EPSF  1e-5f

// ---------------- scratch (static device arrays; no cudaMalloc) -------------
__device__ __half g_xq[(size_t)BATCH * IN_F];    // 32 MB quantized activations
__device__ __half g_wbin[(size_t)OUT_F * IN_F];  // 8 MB  sign weights
__device__ float  g_beta[OUT_F];
__device__ float  g_rs[BATCH];

// ---------------- fused prep: register-resident rows ------------------------
__global__ __launch_bounds__(256) void prep_kernel(const float* __restrict__ x,
                                                   const float* __restrict__ w) {
    const int tid = threadIdx.x, lane = tid & 31, wid = tid >> 5;
    __shared__ float red[3][8];

    float v[8];
    if (blockIdx.x < 2048) {
        const int o = blockIdx.x;
        const float4* row = (const float4*)(w + (size_t)o * IN_F) + tid * 2;
        float4 p0 = row[0], p1 = row[1];
        v[0]=p0.x; v[1]=p0.y; v[2]=p0.z; v[3]=p0.w;
        v[4]=p1.x; v[5]=p1.y; v[6]=p1.z; v[7]=p1.w;

        float s0 = 0.f, s1 = 0.f;
        #pragma unroll
        for (int i = 0; i < 8; i++) { s0 += v[i]; s1 += fabsf(v[i]); }
        #pragma unroll
        for (int off = 16; off; off >>= 1) {
            s0 += __shfl_xor_sync(0xffffffffu, s0, off);
            s1 += __shfl_xor_sync(0xffffffffu, s1, off);
        }
        if (lane == 0) { red[0][wid] = s0; red[1][wid] = s1; }
        __syncthreads();
        float t0 = 0.f, t1 = 0.f;
        #pragma unroll
        for (int i = 0; i < 8; i++) { t0 += red[0][i]; t1 += red[1][i]; }
        float mean = t0 * (1.0f / IN_F);
        if (tid == 0) g_beta[o] = t1 * (1.0f / IN_F);

        __half h[8];
        #pragma unroll
        for (int i = 0; i < 8; i++) {
            float c = v[i] - mean;
            h[i] = __float2half_rn((c > 0.f) ? 1.0f : ((c < 0.f) ? -1.0f : 0.0f));
        }
        *((uint4*)(g_wbin + (size_t)o * IN_F) + tid) = *(const uint4*)h;
    } else {
        const int b = blockIdx.x - 2048;
        const float4* row = (const float4*)(x + (size_t)b * IN_F) + tid * 2;
        float4 p0 = row[0], p1 = row[1];
        v[0]=p0.x; v[1]=p0.y; v[2]=p0.z; v[3]=p0.w;
        v[4]=p1.x; v[5]=p1.y; v[6]=p1.z; v[7]=p1.w;

        float s0 = 0.f, s1 = 0.f;
        #pragma unroll
        for (int i = 0; i < 8; i++) { s0 += v[i]; s1 += v[i] * v[i]; }
        #pragma unroll
        for (int off = 16; off; off >>= 1) {
            s0 += __shfl_xor_sync(0xffffffffu, s0, off);
            s1 += __shfl_xor_sync(0xffffffffu, s1, off);
        }
        if (lane == 0) { red[0][wid] = s0; red[1][wid] = s1; }
        __syncthreads();
        float t0 = 0.f, t1 = 0.f;
        #pragma unroll
        for (int i = 0; i < 8; i++) { t0 += red[0][i]; t1 += red[1][i]; }
        float mu   = t0 * (1.0f / IN_F);
        float var  = t1 * (1.0f / IN_F) - mu * mu;
        float rstd = rsqrtf(var + EPSF);

        float lm = 0.f;
        #pragma unroll
        for (int i = 0; i < 8; i++) lm = fmaxf(lm, fabsf(v[i] - mu));
        #pragma unroll
        for (int off = 16; off; off >>= 1)
            lm = fmaxf(lm, __shfl_xor_sync(0xffffffffu, lm, off));
        if (lane == 0) red[2][wid] = lm;
        __syncthreads();
        float mx = 0.f;
        #pragma unroll
        for (int i = 0; i < 8; i++) mx = fmaxf(mx, red[2][i]);
        float gama = fmaxf(mx * rstd, EPSF);
        float s = rstd * (QB / gama);
        const float clo = -QB + EPSF, chi = QB - EPSF;

        __half h[8];
        #pragma unroll
        for (int i = 0; i < 8; i++) {
            float q = (v[i] - mu) * s;
            h[i] = __float2half_rn(fminf(fmaxf(q, clo), chi));
        }
        *((uint4*)(g_xq + (size_t)b * IN_F) + tid) = *(const uint4*)h;
        if (tid == 0) g_rs[b] = gama * (1.0f / QB);
    }
    // PDL: allow dependent GEMM launch once all CTAs reach here (stores done)
    cudaTriggerProgrammaticLaunchCompletion();
}

// ---------------- GEMM: y = xq @ wbin^T, mbarrier pipeline (R11 config) ----
#define BM 128
#define BN 128
#define BK 64
#define SST 72            // smem row stride in halves (144B rows, conflict-free)
#define KT  (IN_F / BK)   // 32
#define NSTG 3
#define NTHR 256

__device__ __forceinline__ void mma_f16(float* c, const uint32_t* a, const uint32_t* b) {
    asm volatile(
        "mma.sync.aligned.m16n8k16.row.col.f32.f16.f16.f32 "
        "{%0,%1,%2,%3}, {%4,%5,%6,%7}, {%8,%9}, {%0,%1,%2,%3};\n"
        : "+f"(c[0]), "+f"(c[1]), "+f"(c[2]), "+f"(c[3])
        : "r"(a[0]), "r"(a[1]), "r"(a[2]), "r"(a[3]), "r"(b[0]), "r"(b[1]));
}

__device__ __forceinline__ void ldsm4(uint32_t* r, uint32_t addr) {
    asm volatile("ldmatrix.sync.aligned.m8n8.x4.shared.b16 {%0,%1,%2,%3}, [%4];\n"
                 : "=r"(r[0]), "=r"(r[1]), "=r"(r[2]), "=r"(r[3]) : "r"(addr));
}

__device__ __forceinline__ void cpa16(uint32_t d, const void* s) {
    asm volatile("cp.async.cg.shared.global [%0], [%1], 16;\n" :: "r"(d), "l"(s));
}
__device__ __forceinline__ void mbar_init(uint32_t a, uint32_t cnt) {
    asm volatile("mbarrier.init.shared.b64 [%0], %1;" :: "r"(a), "r"(cnt) : "memory");
}
__device__ __forceinline__ void mbar_arrive(uint32_t a) {
    asm volatile("mbarrier.arrive.shared.b64 _, [%0];" :: "r"(a) : "memory");
}
__device__ __forceinline__ void cpa_mbar_arrive_noinc(uint32_t a) {
    asm volatile("cp.async.mbarrier.arrive.noinc.shared.b64 [%0];" :: "r"(a) : "memory");
}
__device__ __forceinline__ void mbar_wait(uint32_t a, uint32_t parity) {
    asm volatile(
        "{\n\t.reg .pred P;\n\t"
        "LW%=:\n\t"
        "mbarrier.try_wait.parity.acquire.cta.shared::cta.b64 P, [%0], %1, 0x989680;\n\t"
        "@P bra LD%=;\n\t"
        "bra LW%=;\n\t"
        "LD%=:\n\t}"
        :: "r"(a), "r"(parity) : "memory");
}

__global__ __launch_bounds__(NTHR, 2) void gemm_kernel(const float* __restrict__ bias,
                                                       float* __restrict__ out) {
    extern __shared__ __half sm[];
    // layout: [0,64): mbarriers (full[3] @0,8,16; empty[3] @24,32,40); tiles @64
    __half* sA = sm + 32;                        // NSTG * BM * SST halves
    __half* sB = sm + 32 + NSTG * BM * SST;      // NSTG * BN * SST halves
    const uint32_t mbarBase = (uint32_t)__cvta_generic_to_shared(sm);
    const uint32_t fullM  = mbarBase;            // + 8*s
    const uint32_t emptyM = mbarBase + 24;       // + 8*s

    const int tid = threadIdx.x;
    const int lane = tid & 31, w = tid >> 5;
    const int wm = w >> 2, wn = w & 3;           // 2x4 warp grid, warp tile 64x32
    const int warp_m = wm * 64, warp_n = wn * 32;
    const int m0 = blockIdx.y * BM;
    const int n0 = blockIdx.x * BN;

    const uint32_t baseA = (uint32_t)__cvta_generic_to_shared(sA);
    const uint32_t baseB = (uint32_t)__cvta_generic_to_shared(sB);

    const __half* __restrict__ Aq = g_xq;
    const __half* __restrict__ Bw = g_wbin;

    // per-lane ldmatrix address components
    const int matA = lane >> 3, ra = lane & 7;
    const int a_row_off = (matA & 1) * 8 + ra;
    const int a_col_off = (matA >> 1) * 8;
    const int b_n_off   = ((matA >> 1) ? 8 : 0) + ra;
    const int b_k_off   = (matA & 1) * 8;

    float acc[4][4][4];
    #pragma unroll
    for (int a = 0; a < 4; a++)
        #pragma unroll
        for (int b = 0; b < 4; b++)
            #pragma unroll
            for (int c = 0; c < 4; c++) acc[a][b][c] = 0.f;

    if (tid == 0) {
        #pragma unroll
        for (int s = 0; s < NSTG; s++) {
            mbar_init(fullM + 8 * s, NTHR);   // 256 async arrivals per load
            mbar_init(emptyM + 8 * s, 8);     // 8 warp-arrivals per consume
        }
    }
    __syncthreads();

    // PDL: preamble above overlaps prep's tail; block here until prep's
    // stores (g_xq/g_wbin/g_rs/g_beta) are visible.
    cudaGridDependencySynchronize();

    // tile loader: A 1024 + B 1024 chunks of 16B; 8 per thread; signals full[s]
    auto load_tile = [&](int kt, int buf) {
        const int k0 = kt * BK;
        #pragma unroll
        for (int i = 0; i < 4; i++) {
            int c = tid + i * NTHR;
            int r = c >> 3, kc = c & 7;
            uint32_t doff = (uint32_t)((buf * BM * SST + r * SST + kc * 8) * 2);
            cpa16(baseA + doff, Aq + (size_t)(m0 + r) * IN_F + k0 + kc * 8);
        }
        #pragma unroll
        for (int i = 0; i < 4; i++) {
            int c = tid + i * NTHR;
            int r = c >> 3, kc = c & 7;
            uint32_t doff = (uint32_t)((buf * BN * SST + r * SST + kc * 8) * 2);
            cpa16(baseB + doff, Bw + (size_t)(n0 + r) * IN_F + k0 + kc * 8);
        }
        cpa_mbar_arrive_noinc(fullM + 8 * buf);
    };

    load_tile(0, 0);
    load_tile(1, 1);

    for (int kt = 0; kt < KT; ++kt) {
        const int s = kt % NSTG;
        mbar_wait(fullM + 8 * s, (kt / NSTG) & 1);

        const uint32_t bufAEl = (uint32_t)(s * BM * SST);
        const uint32_t bufBEl = (uint32_t)(s * BN * SST);
        #pragma unroll
        for (int ks = 0; ks < 4; ++ks) {
            uint32_t aa[4][4], bb[2][4];
            #pragma unroll
            for (int mt = 0; mt < 4; ++mt) {
                uint32_t off = (bufAEl + (uint32_t)((warp_m + mt * 16 + a_row_off) * SST
                                                    + ks * 16 + a_col_off)) * 2;
                ldsm4(aa[mt], baseA + off);
            }
            #pragma unroll
            for (int p = 0; p < 2; ++p) {
                uint32_t off = (bufBEl + (uint32_t)((warp_n + p * 16 + b_n_off) * SST
                                                    + ks * 16 + b_k_off)) * 2;
                ldsm4(bb[p], baseB + off);
            }
            #pragma unroll
            for (int mt = 0; mt < 4; ++mt)
                #pragma unroll
                for (int p = 0; p < 2; ++p) {
                    mma_f16(acc[mt][2 * p],     aa[mt], &bb[p][0]);
                    mma_f16(acc[mt][2 * p + 1], aa[mt], &bb[p][2]);
                }
        }

        // done reading stage s
        __syncwarp();
        if (lane == 0) mbar_arrive(emptyM + 8 * s);

        // load tile kt+2 into stage s2=(kt+2)%3; prior tenant = tile kt-1
        if (kt + 2 < KT) {
            const int s2 = (kt + 2) % NSTG;
            if (kt >= 1) mbar_wait(emptyM + 8 * s2, ((kt - 1) / NSTG) & 1);
            load_tile(kt + 2, s2);
        }
    }

    // epilogue: y = acc * beta[n] * rs[m] + bias[n]
    const int l4 = lane >> 2, l2 = (lane & 3) * 2;
    #pragma unroll
    for (int mt = 0; mt < 4; ++mt) {
        int mrow = m0 + warp_m + mt * 16 + l4;
        float s0 = g_rs[mrow];
        float s1 = g_rs[mrow + 8];
        #pragma unroll
        for (int nt = 0; nt < 4; ++nt) {
            int n = n0 + warp_n + nt * 8 + l2;
            float be0 = g_beta[n], be1 = g_beta[n + 1];
            float bi0 = bias[n],   bi1 = bias[n + 1];
            float2 r0, r1;
            r0.x = acc[mt][nt][0] * be0 * s0 + bi0;
            r0.y = acc[mt][nt][1] * be1 * s0 + bi1;
            r1.x = acc[mt][nt][2] * be0 * s1 + bi0;
            r1.y = acc[mt][nt][3] * be1 * s1 + bi1;
            *reinterpret_cast<float2*>(out + (size_t)mrow * OUT_F + n) = r0;
            *reinterpret_cast<float2*>(out + (size_t)(mrow + 8) * OUT_F + n) = r1;
        }
    }
}

// ---------------- launch ----------------------------------------------------
extern "C" void kernel_launch(void* const* d_in, const int* in_sizes, int n_in,
                              void* d_out, int out_size) {
    const float* x    = (const float*)d_in[0];
    const float* wgt  = (const float*)d_in[1];
    const float* bias = (const float*)d_in[2];
    float* out = (float*)d_out;

    prep_kernel<<<2048 + BATCH, 256>>>(x, wgt);

    const int smem = 64 + NSTG * (BM + BN) * SST * (int)sizeof(__half);  // 110656
    cudaFuncSetAttribute(gemm_kernel, cudaFuncAttributeMaxDynamicSharedMemorySize, smem);

    cudaLaunchConfig_t cfg = {};
    cfg.gridDim = dim3(OUT_F / BN, BATCH / BM);   // (16, 64) = 1024 CTAs
    cfg.blockDim = dim3(NTHR);
    cfg.dynamicSmemBytes = smem;
    cfg.stream = 0;
    cudaLaunchAttribute attrs[1];
    attrs[0].id = cudaLaunchAttributeProgrammaticStreamSerialization;
    attrs[0].val.programmaticStreamSerializationAllowed = 1;
    cfg.attrs = attrs;
    cfg.numAttrs = 1;
    cudaLaunchKernelEx(&cfg, gemm_kernel, bias, out);
}

// round 15
// speedup vs baseline: 1.2208x; 1.0901x over previous
#include <cuda_runtime.h>
#include <cuda_fp16.h>
#include <cstdint>

#define BATCH 8192
#define IN_F  2048
#define OUT_F 2048
#define QB    7.0f
#define EPSF  1e-5f

// ---------------- scratch (static device arrays; no cudaMalloc) -------------
__device__ __half g_xq[(size_t)BATCH * IN_F];    // 32 MB quantized activations
__device__ __half g_wbin[(size_t)OUT_F * IN_F];  // 8 MB  sign weights
__device__ float  g_beta[OUT_F];
__device__ float  g_rs[BATCH];

// ---------------- fused prep: register-resident rows ------------------------
__global__ __launch_bounds__(256) void prep_kernel(const float* __restrict__ x,
                                                   const float* __restrict__ w) {
    const int tid = threadIdx.x, lane = tid & 31, wid = tid >> 5;
    __shared__ float red[3][8];

    float v[8];
    if (blockIdx.x < 2048) {
        const int o = blockIdx.x;
        const float4* row = (const float4*)(w + (size_t)o * IN_F) + tid * 2;
        float4 p0 = row[0], p1 = row[1];
        v[0]=p0.x; v[1]=p0.y; v[2]=p0.z; v[3]=p0.w;
        v[4]=p1.x; v[5]=p1.y; v[6]=p1.z; v[7]=p1.w;

        float s0 = 0.f, s1 = 0.f;
        #pragma unroll
        for (int i = 0; i < 8; i++) { s0 += v[i]; s1 += fabsf(v[i]); }
        #pragma unroll
        for (int off = 16; off; off >>= 1) {
            s0 += __shfl_xor_sync(0xffffffffu, s0, off);
            s1 += __shfl_xor_sync(0xffffffffu, s1, off);
        }
        if (lane == 0) { red[0][wid] = s0; red[1][wid] = s1; }
        __syncthreads();
        float t0 = 0.f, t1 = 0.f;
        #pragma unroll
        for (int i = 0; i < 8; i++) { t0 += red[0][i]; t1 += red[1][i]; }
        float mean = t0 * (1.0f / IN_F);
        if (tid == 0) g_beta[o] = t1 * (1.0f / IN_F);

        __half h[8];
        #pragma unroll
        for (int i = 0; i < 8; i++) {
            float c = v[i] - mean;
            h[i] = __float2half_rn((c > 0.f) ? 1.0f : ((c < 0.f) ? -1.0f : 0.0f));
        }
        *((uint4*)(g_wbin + (size_t)o * IN_F) + tid) = *(const uint4*)h;
    } else {
        const int b = blockIdx.x - 2048;
        const float4* row = (const float4*)(x + (size_t)b * IN_F) + tid * 2;
        float4 p0 = row[0], p1 = row[1];
        v[0]=p0.x; v[1]=p0.y; v[2]=p0.z; v[3]=p0.w;
        v[4]=p1.x; v[5]=p1.y; v[6]=p1.z; v[7]=p1.w;

        float s0 = 0.f, s1 = 0.f;
        #pragma unroll
        for (int i = 0; i < 8; i++) { s0 += v[i]; s1 += v[i] * v[i]; }
        #pragma unroll
        for (int off = 16; off; off >>= 1) {
            s0 += __shfl_xor_sync(0xffffffffu, s0, off);
            s1 += __shfl_xor_sync(0xffffffffu, s1, off);
        }
        if (lane == 0) { red[0][wid] = s0; red[1][wid] = s1; }
        __syncthreads();
        float t0 = 0.f, t1 = 0.f;
        #pragma unroll
        for (int i = 0; i < 8; i++) { t0 += red[0][i]; t1 += red[1][i]; }
        float mu   = t0 * (1.0f / IN_F);
        float var  = t1 * (1.0f / IN_F) - mu * mu;
        float rstd = rsqrtf(var + EPSF);

        float lm = 0.f;
        #pragma unroll
        for (int i = 0; i < 8; i++) lm = fmaxf(lm, fabsf(v[i] - mu));
        #pragma unroll
        for (int off = 16; off; off >>= 1)
            lm = fmaxf(lm, __shfl_xor_sync(0xffffffffu, lm, off));
        if (lane == 0) red[2][wid] = lm;
        __syncthreads();
        float mx = 0.f;
        #pragma unroll
        for (int i = 0; i < 8; i++) mx = fmaxf(mx, red[2][i]);
        float gama = fmaxf(mx * rstd, EPSF);
        float s = rstd * (QB / gama);
        const float clo = -QB + EPSF, chi = QB - EPSF;

        __half h[8];
        #pragma unroll
        for (int i = 0; i < 8; i++) {
            float q = (v[i] - mu) * s;
            h[i] = __float2half_rn(fminf(fmaxf(q, clo), chi));
        }
        *((uint4*)(g_xq + (size_t)b * IN_F) + tid) = *(const uint4*)h;
        if (tid == 0) g_rs[b] = gama * (1.0f / QB);
    }
    cudaTriggerProgrammaticLaunchCompletion();
}

// ---------------- GEMM: y = xq @ wbin^T, mbarrier pipeline, kt unroll x3 ---
#define BM 128
#define BN 128
#define BK 64
#define SST 72            // smem row stride in halves (144B rows, conflict-free)
#define KT  (IN_F / BK)   // 32
#define NSTG 3
#define NTHR 256

__device__ __forceinline__ void mma_f16(float* c, const uint32_t* a, const uint32_t* b) {
    asm volatile(
        "mma.sync.aligned.m16n8k16.row.col.f32.f16.f16.f32 "
        "{%0,%1,%2,%3}, {%4,%5,%6,%7}, {%8,%9}, {%0,%1,%2,%3};\n"
        : "+f"(c[0]), "+f"(c[1]), "+f"(c[2]), "+f"(c[3])
        : "r"(a[0]), "r"(a[1]), "r"(a[2]), "r"(a[3]), "r"(b[0]), "r"(b[1]));
}

__device__ __forceinline__ void ldsm4(uint32_t* r, uint32_t addr) {
    asm volatile("ldmatrix.sync.aligned.m8n8.x4.shared.b16 {%0,%1,%2,%3}, [%4];\n"
                 : "=r"(r[0]), "=r"(r[1]), "=r"(r[2]), "=r"(r[3]) : "r"(addr));
}

__device__ __forceinline__ void cpa16(uint32_t d, const void* s) {
    asm volatile("cp.async.cg.shared.global [%0], [%1], 16;\n" :: "r"(d), "l"(s));
}
__device__ __forceinline__ void mbar_init(uint32_t a, uint32_t cnt) {
    asm volatile("mbarrier.init.shared.b64 [%0], %1;" :: "r"(a), "r"(cnt) : "memory");
}
__device__ __forceinline__ void mbar_arrive(uint32_t a) {
    asm volatile("mbarrier.arrive.shared.b64 _, [%0];" :: "r"(a) : "memory");
}
__device__ __forceinline__ void cpa_mbar_arrive_noinc(uint32_t a) {
    asm volatile("cp.async.mbarrier.arrive.noinc.shared.b64 [%0];" :: "r"(a) : "memory");
}
__device__ __forceinline__ void mbar_wait(uint32_t a, uint32_t parity) {
    asm volatile(
        "{\n\t.reg .pred P;\n\t"
        "LW%=:\n\t"
        "mbarrier.try_wait.parity.acquire.cta.shared::cta.b64 P, [%0], %1, 0x989680;\n\t"
        "@P bra LD%=;\n\t"
        "bra LW%=;\n\t"
        "LD%=:\n\t}"
        :: "r"(a), "r"(parity) : "memory");
}

__global__ __launch_bounds__(NTHR, 2) void gemm_kernel(const float* __restrict__ bias,
                                                       float* __restrict__ out) {
    extern __shared__ __half sm[];
    __half* sA = sm + 32;                        // NSTG * BM * SST halves
    __half* sB = sm + 32 + NSTG * BM * SST;      // NSTG * BN * SST halves
    const uint32_t mbarBase = (uint32_t)__cvta_generic_to_shared(sm);
    const uint32_t fullM  = mbarBase;            // + 8*s
    const uint32_t emptyM = mbarBase + 24;       // + 8*s

    const int tid = threadIdx.x;
    const int lane = tid & 31, w = tid >> 5;
    const int wm = w >> 2, wn = w & 3;           // 2x4 warp grid, warp tile 64x32
    const int warp_m = wm * 64, warp_n = wn * 32;
    const int m0 = blockIdx.y * BM;
    const int n0 = blockIdx.x * BN;

    const uint32_t baseA = (uint32_t)__cvta_generic_to_shared(sA);
    const uint32_t baseB = (uint32_t)__cvta_generic_to_shared(sB);

    const __half* __restrict__ Aq = g_xq;
    const __half* __restrict__ Bw = g_wbin;

    const int matA = lane >> 3, ra = lane & 7;
    const int a_row_off = (matA & 1) * 8 + ra;
    const int a_col_off = (matA >> 1) * 8;
    const int b_n_off   = ((matA >> 1) ? 8 : 0) + ra;
    const int b_k_off   = (matA & 1) * 8;

    // loop-invariant per-lane base addresses (stage offset added as immediate)
    uint32_t aRow[4], bRow[2];
    #pragma unroll
    for (int mt = 0; mt < 4; ++mt)
        aRow[mt] = baseA + (uint32_t)((warp_m + mt * 16 + a_row_off) * SST + a_col_off) * 2;
    #pragma unroll
    for (int p = 0; p < 2; ++p)
        bRow[p] = baseB + (uint32_t)((warp_n + p * 16 + b_n_off) * SST + b_k_off) * 2;

    float acc[4][4][4];
    #pragma unroll
    for (int a = 0; a < 4; a++)
        #pragma unroll
        for (int b = 0; b < 4; b++)
            #pragma unroll
            for (int c = 0; c < 4; c++) acc[a][b][c] = 0.f;

    if (tid == 0) {
        #pragma unroll
        for (int s = 0; s < NSTG; s++) {
            mbar_init(fullM + 8 * s, NTHR);
            mbar_init(emptyM + 8 * s, 8);
        }
    }
    __syncthreads();
    cudaGridDependencySynchronize();

    auto load_tile = [&](int kt, int buf) {
        const int k0 = kt * BK;
        #pragma unroll
        for (int i = 0; i < 4; i++) {
            int c = tid + i * NTHR;
            int r = c >> 3, kc = c & 7;
            uint32_t doff = (uint32_t)((buf * BM * SST + r * SST + kc * 8) * 2);
            cpa16(baseA + doff, Aq + (size_t)(m0 + r) * IN_F + k0 + kc * 8);
        }
        #pragma unroll
        for (int i = 0; i < 4; i++) {
            int c = tid + i * NTHR;
            int r = c >> 3, kc = c & 7;
            uint32_t doff = (uint32_t)((buf * BN * SST + r * SST + kc * 8) * 2);
            cpa16(baseB + doff, Bw + (size_t)(n0 + r) * IN_F + k0 + kc * 8);
        }
        cpa_mbar_arrive_noinc(fullM + 8 * buf);
    };

    // compute one ktile resident in compile-time stage S
    auto compute_stage = [&](int S_imm) {
        const uint32_t aOff = (uint32_t)(S_imm * BM * SST * 2);
        const uint32_t bOff = (uint32_t)(S_imm * BN * SST * 2);
        #pragma unroll
        for (int ks = 0; ks < 4; ++ks) {
            uint32_t aa[4][4], bb[2][4];
            #pragma unroll
            for (int mt = 0; mt < 4; ++mt)
                ldsm4(aa[mt], aRow[mt] + aOff + (uint32_t)(ks * 32));
            #pragma unroll
            for (int p = 0; p < 2; ++p)
                ldsm4(bb[p], bRow[p] + bOff + (uint32_t)(ks * 32));
            #pragma unroll
            for (int mt = 0; mt < 4; ++mt)
                #pragma unroll
                for (int p = 0; p < 2; ++p) {
                    mma_f16(acc[mt][2 * p],     aa[mt], &bb[p][0]);
                    mma_f16(acc[mt][2 * p + 1], aa[mt], &bb[p][2]);
                }
        }
    };

    load_tile(0, 0);
    load_tile(1, 1);

    // KT = 32 = 3*10 + 2: 10 triple iterations, 2-tile tail
    for (int j = 0; j < 10; ++j) {
        const uint32_t pj  = (uint32_t)(j & 1);
        const uint32_t pj1 = (uint32_t)((j - 1) & 1);
        // ---- u=0: kt=3j, stage 0
        mbar_wait(fullM + 0, pj);
        compute_stage(0);
        __syncwarp();
        if (lane == 0) mbar_arrive(emptyM + 0);
        if (j >= 1) mbar_wait(emptyM + 16, pj1);   // stage 2, prior tile 3j-1
        load_tile(3 * j + 2, 2);
        // ---- u=1: kt=3j+1, stage 1
        mbar_wait(fullM + 8, pj);
        compute_stage(1);
        __syncwarp();
        if (lane == 0) mbar_arrive(emptyM + 8);
        mbar_wait(emptyM + 0, pj);                 // stage 0, prior tile 3j
        load_tile(3 * j + 3, 0);
        // ---- u=2: kt=3j+2, stage 2
        mbar_wait(fullM + 16, pj);
        compute_stage(2);
        __syncwarp();
        if (lane == 0) mbar_arrive(emptyM + 16);
        mbar_wait(emptyM + 8, pj);                 // stage 1, prior tile 3j+1
        load_tile(3 * j + 4, 1);
    }
    // tail: kt=30 (stage 0, parity (30/3)&1=0), kt=31 (stage 1, parity 0)
    mbar_wait(fullM + 0, 0);
    compute_stage(0);
    mbar_wait(fullM + 8, 0);
    compute_stage(1);

    // epilogue: y = acc * beta[n] * rs[m] + bias[n]
    const int l4 = lane >> 2, l2 = (lane & 3) * 2;
    #pragma unroll
    for (int mt = 0; mt < 4; ++mt) {
        int mrow = m0 + warp_m + mt * 16 + l4;
        float s0 = g_rs[mrow];
        float s1 = g_rs[mrow + 8];
        #pragma unroll
        for (int nt = 0; nt < 4; ++nt) {
            int n = n0 + warp_n + nt * 8 + l2;
            float be0 = g_beta[n], be1 = g_beta[n + 1];
            float bi0 = bias[n],   bi1 = bias[n + 1];
            float2 r0, r1;
            r0.x = acc[mt][nt][0] * be0 * s0 + bi0;
            r0.y = acc[mt][nt][1] * be1 * s0 + bi1;
            r1.x = acc[mt][nt][2] * be0 * s1 + bi0;
            r1.y = acc[mt][nt][3] * be1 * s1 + bi1;
            *reinterpret_cast<float2*>(out + (size_t)mrow * OUT_F + n) = r0;
            *reinterpret_cast<float2*>(out + (size_t)(mrow + 8) * OUT_F + n) = r1;
        }
    }
}

// ---------------- launch ----------------------------------------------------
extern "C" void kernel_launch(void* const* d_in, const int* in_sizes, int n_in,
                              void* d_out, int out_size) {
    const float* x    = (const float*)d_in[0];
    const float* wgt  = (const float*)d_in[1];
    const float* bias = (const float*)d_in[2];
    float* out = (float*)d_out;

    prep_kernel<<<2048 + BATCH, 256>>>(x, wgt);

    const int smem = 64 + NSTG * (BM + BN) * SST * (int)sizeof(__half);  // 110656
    cudaFuncSetAttribute(gemm_kernel, cudaFuncAttributeMaxDynamicSharedMemorySize, smem);

    cudaLaunchConfig_t cfg = {};
    cfg.gridDim = dim3(OUT_F / BN, BATCH / BM);   // (16, 64) = 1024 CTAs
    cfg.blockDim = dim3(NTHR);
    cfg.dynamicSmemBytes = smem;
    cfg.stream = 0;
    cudaLaunchAttribute attrs[1];
    attrs[0].id = cudaLaunchAttributeProgrammaticStreamSerialization;
    attrs[0].val.programmaticStreamSerializationAllowed = 1;
    cfg.attrs = attrs;
    cfg.numAttrs = 1;
    cudaLaunchKernelEx(&cfg, gemm_kernel, bias, out);
}